// round 1
// baseline (speedup 1.0000x reference)
#include <cuda_runtime.h>

// Problem constants (from reference: B=2048, N=60, C=128)
#define BCOL 2048
#define NL   60
#define CCH  128
#define BLOCK 128

// dynamic smem: two per-thread arrays of NL floats, laid out [layer][thread]
#define SMEM_FLOATS (2 * NL * BLOCK)
#define SMEM_BYTES  (SMEM_FLOATS * sizeof(float))

__global__ __launch_bounds__(BLOCK)
void adding_doubling_kernel(const float* __restrict__ a,
                            const float* __restrict__ r,
                            const float* __restrict__ t,
                            const float* __restrict__ s,
                            float* __restrict__ out)
{
    extern __shared__ float smem[];
    float* sh_d = smem;                 // ds[l], later overwritten by dt[l]
    float* sh_r = smem + NL * BLOCK;    // rs[l], later overwritten by rt[l]
    const int tx = threadIdx.x;

    int tid = blockIdx.x * BLOCK + tx;
    if (tid >= BCOL * CCH) return;

    const int b = tid >> 7;          // tid / CCH
    const int c = tid & (CCH - 1);   // tid % CCH
    const size_t base = (size_t)b * (NL * CCH) + c;
    const size_t BNC  = (size_t)BCOL * NL * CCH;

    float* fd = out;            // flux_down
    float* fu = out + BNC;      // flux_up
    float* ab = out + 2 * BNC;  // absorbed

#define SH_D(l) sh_d[(l) * BLOCK + tx]
#define SH_R(l) sh_r[(l) * BLOCK + tx]

    // ---------------- Phase A: bottom-up cumulative surface reflection ----
    // rs[N-1] = r[N-1]; for l = N-2..0:
    //   ds[l] = 1/(1 - rs[l+1]*r[l]);  rs[l] = r[l] + rs[l+1]*t[l]^2*ds[l]
    {
        float rs_run = r[base + (size_t)(NL - 1) * CCH];
        SH_R(NL - 1) = rs_run;
        #pragma unroll 4
        for (int l = NL - 2; l >= 0; --l) {
            size_t idx = base + (size_t)l * CCH;
            float rl = r[idx];
            float tl = t[idx];
            float dd = 1.0f / (1.0f - rs_run * rl);
            SH_D(l) = dd;
            rs_run = rl + rs_run * tl * tl * dd;
            SH_R(l) = rs_run;
        }
    }

    // ---------------- Phase B: forward — down flux + top-down rt/dt -------
    // down flux (i = l-1):
    //   s_down[i] = ds[i]*(s[i] + s[i+1]*r[i])
    //   G = F + s_down[i];  flux_down[l] = G
    //   absorbed_down[l] = a[l]*(1 + rs[l+1]*t[l]*ds[l]) * G   (l < N-1)
    //   F = G * t[l]*ds[l]
    //   at l = N-1: absorbed_down[N-1] = a[N-1]*G
    // rt/dt (overwrite smem in place; ds[l], rs[l+1] are dead after use):
    //   dt[l] = 1/(1 - rt_run*r[l]); rt[l] = r[l] + rt_run*t[l]^2*dt[l]
    {
        float s_prev = s[base];
        float r_prev = r[base];
        float ds_prev = SH_D(0);     // ds[0], read before overwrite
        float rt_run = r_prev;       // rt[0] = r[0]
        SH_R(0) = rt_run;
        SH_D(0) = 1.0f;              // dt[0] (by convention; unused in scans)
        fd[base] = 0.0f;             // flux_down[0]
        ab[base] = 0.0f;             // absorbed_down[0] (final value set in C)

        float F = 0.0f;
        #pragma unroll 4
        for (int l = 1; l < NL; ++l) {
            size_t idx = base + (size_t)l * CCH;
            float sl = s[idx];
            float rl = r[idx];
            float tl = t[idx];
            float al = a[idx];

            float s_down = ds_prev * (s_prev + sl * r_prev);
            float G = F + s_down;
            fd[idx] = G;

            float absd;
            if (l < NL - 1) {
                float dsl  = SH_D(l);       // ds[l]
                float rsl1 = SH_R(l + 1);   // rs[l+1]
                float td = tl * dsl;
                absd = al * (1.0f + rsl1 * td) * G;
                F = G * td;
                ds_prev = dsl;
            } else {
                absd = al * G;
            }
            ab[idx] = absd;

            // rt/dt update, overwriting dead ds[l]/rs[l] slots
            float dd = 1.0f / (1.0f - rt_run * rl);
            SH_D(l) = dd;                    // dt[l]
            rt_run = rl + rt_run * tl * tl * dd;
            SH_R(l) = rt_run;                // rt[l]

            s_prev = sl;
            r_prev = rl;
        }
    }

    // ---------------- Phase C: reverse — up flux ---------------------------
    // for m = N-1..2:
    //   s_up[m] = dt[m]*(s[m] + s[m-1]*r[m])
    //   G = Fu + s_up[m]; flux_up[m] = G
    //   absorbed_up[m-1] = G * a[m-1]*(1 + rt[m-2]*t[m-1]*dt[m-1])
    //   Fu = G * t[m-1]*dt[m-1]
    // then: flux1 = Fu + s_up[1]; flux_up[1] = flux1
    //       absorbed[0] = flux1*a[0]; flux_up[0] = flux1*t[0] + s[0]
    {
        float Fu = 0.0f;
        size_t idxN = base + (size_t)(NL - 1) * CCH;
        float s_m = s[idxN];   // s[m]
        float r_m = r[idxN];   // r[m]

        #pragma unroll 4
        for (int m = NL - 1; m >= 2; --m) {
            size_t idxm1 = base + (size_t)(m - 1) * CCH;
            float s_m1 = s[idxm1];
            float r_m1 = r[idxm1];
            float t_m1 = t[idxm1];
            float a_m1 = a[idxm1];

            float dt_m  = SH_D(m);
            float dt_m1 = SH_D(m - 1);
            float rt_m2 = SH_R(m - 2);

            float s_up_m = dt_m * (s_m + s_m1 * r_m);
            float G = Fu + s_up_m;
            fu[base + (size_t)m * CCH] = G;

            float tdm1 = t_m1 * dt_m1;
            float au = G * a_m1 * (1.0f + rt_m2 * tdm1);
            ab[idxm1] += au;             // absorbed[m-1] += up part
            Fu = G * tdm1;

            s_m = s_m1;
            r_m = r_m1;
        }

        // m = 1 and m = 0 tail
        float s0 = s[base];
        float t0 = t[base];
        float a0 = a[base];
        float dt1 = SH_D(1);
        float s_up1 = dt1 * (s_m + s0 * r_m);   // s_m = s[1], r_m = r[1]
        float flux1 = Fu + s_up1;
        fu[base + CCH] = flux1;                  // flux_up[1]
        ab[base] = flux1 * a0;                   // absorbed[0] (down part = 0)
        fu[base] = flux1 * t0 + s0;              // flux_up[0]; s_up[0] = s[0]
    }

#undef SH_D
#undef SH_R
}

extern "C" void kernel_launch(void* const* d_in, const int* in_sizes, int n_in,
                              void* d_out, int out_size)
{
    const float* a = (const float*)d_in[0];
    const float* r = (const float*)d_in[1];
    const float* t = (const float*)d_in[2];
    const float* s = (const float*)d_in[3];
    float* out = (float*)d_out;

    // dynamic smem > 48KB needs the opt-in attribute (host API, not a stream
    // op; graph-capture safe, allocation-free, deterministic)
    cudaFuncSetAttribute(adding_doubling_kernel,
                         cudaFuncAttributeMaxDynamicSharedMemorySize,
                         (int)SMEM_BYTES);

    const int total = BCOL * CCH;                 // 262144 threads
    const int grid = (total + BLOCK - 1) / BLOCK; // 2048 blocks
    adding_doubling_kernel<<<grid, BLOCK, SMEM_BYTES>>>(a, r, t, s, out);
}

// round 2
// speedup vs baseline: 2.4464x; 2.4464x over previous
#include <cuda_runtime.h>

// Problem constants (from reference: B=2048, N=60, C=128)
#define BCOL 2048
#define NL   60
#define CCH  128
#define BLOCK 128

// dynamic smem: ONE per-thread array of NL floats, laid out [layer][thread].
// Holds rs[] during phases A/B, progressively overwritten by rt[] in phase B.
#define SMEM_FLOATS (NL * BLOCK)
#define SMEM_BYTES  (SMEM_FLOATS * sizeof(float))

__device__ __forceinline__ float frcp(float x) {
    // fast reciprocal (MUFU.RCP path); ~2ulp, fine vs 1e-3 tolerance
    return __fdividef(1.0f, x);
}

__global__ __launch_bounds__(BLOCK)
void adding_doubling_kernel(const float* __restrict__ a,
                            const float* __restrict__ r,
                            const float* __restrict__ t,
                            const float* __restrict__ s,
                            float* __restrict__ out)
{
    extern __shared__ float smem[];
    float* sh_r = smem;   // rs[l] (phase A), overwritten by rt[l] (phase B)
    const int tx = threadIdx.x;

    int tid = blockIdx.x * BLOCK + tx;
    if (tid >= BCOL * CCH) return;

    const int b = tid >> 7;          // tid / CCH
    const int c = tid & (CCH - 1);   // tid % CCH
    const size_t base = (size_t)b * (NL * CCH) + c;
    const size_t BNC  = (size_t)BCOL * NL * CCH;

    float* fd = out;            // flux_down
    float* fu = out + BNC;      // flux_up
    float* ab = out + 2 * BNC;  // absorbed

#define SH_R(l) sh_r[(l) * BLOCK + tx]

    // ---------------- Phase A: bottom-up cumulative surface reflection ----
    // rs[N-1] = r[N-1]; for l = N-2..0:
    //   ds[l] = 1/(1 - rs[l+1]*r[l]);  rs[l] = r[l] + rs[l+1]*t[l]^2*ds[l]
    // Only rs[] is stored; ds is recomputed on demand in phase B.
    {
        float rs_run = r[base + (size_t)(NL - 1) * CCH];
        SH_R(NL - 1) = rs_run;
        #pragma unroll 4
        for (int l = NL - 2; l >= 1; --l) {   // rs[0] never consumed
            size_t idx = base + (size_t)l * CCH;
            float rl = r[idx];
            float tl = t[idx];
            float dd = frcp(1.0f - rs_run * rl);
            rs_run = rl + rs_run * tl * tl * dd;
            SH_R(l) = rs_run;
        }
    }

    // ---------------- Phase B: forward — down flux + top-down rt ----------
    // s_down[l-1] = ds[l-1]*(s[l-1] + s[l]*r[l-1])
    // G = F + s_down;  flux_down[l] = G
    // absorbed_down[l] = a[l]*(1 + rs[l+1]*t[l]*ds[l]) * G   (l < N-1)
    // F = G * t[l]*ds[l];   at l = N-1: absorbed_down = a[N-1]*G
    // rt recurrence (overwrites rs[l] slot after rs[l] is dead):
    //   dtl = 1/(1 - rt_run*r[l]); rt[l] = r[l] + rt_run*t[l]^2*dtl
    {
        float s_prev = s[base];
        float r_prev = r[base];
        float rs1 = SH_R(1);
        float ds_prev = frcp(1.0f - rs1 * r_prev);   // ds[0]
        float rt_run = r_prev;                        // rt[0] = r[0]
        SH_R(0) = rt_run;
        fd[base] = 0.0f;             // flux_down[0]
        ab[base] = 0.0f;             // absorbed[0] placeholder (set in C)

        float F = 0.0f;
        #pragma unroll 4
        for (int l = 1; l < NL; ++l) {
            size_t idx = base + (size_t)l * CCH;
            float sl = s[idx];
            float rl = r[idx];
            float tl = t[idx];
            float al = a[idx];

            float s_down = ds_prev * (s_prev + sl * r_prev);
            float G = F + s_down;
            fd[idx] = G;

            float absd;
            if (l < NL - 1) {
                float rsl1 = SH_R(l + 1);               // rs[l+1]
                float dsl  = frcp(1.0f - rsl1 * rl);    // ds[l]
                float td = tl * dsl;
                absd = al * (1.0f + rsl1 * td) * G;
                F = G * td;
                ds_prev = dsl;
            } else {
                absd = al * G;
            }
            ab[idx] = absd;

            // rt update; overwrite dead rs[l] slot with rt[l]
            float dd = frcp(1.0f - rt_run * rl);
            rt_run = rl + rt_run * tl * tl * dd;
            SH_R(l) = rt_run;

            s_prev = sl;
            r_prev = rl;
        }
    }

    // ---------------- Phase C: reverse — up flux ---------------------------
    // dt[m] = 1/(1 - rt[m-1]*r[m]) (recomputed, carried across iterations)
    // s_up[m] = dt[m]*(s[m] + s[m-1]*r[m])
    // G = Fu + s_up[m]; flux_up[m] = G
    // absorbed_up[m-1] = G * a[m-1]*(1 + rt[m-2]*t[m-1]*dt[m-1])
    // Fu = G * t[m-1]*dt[m-1]
    {
        float Fu = 0.0f;
        size_t idxN = base + (size_t)(NL - 1) * CCH;
        float s_m = s[idxN];
        float r_m = r[idxN];
        float rt_m1 = SH_R(NL - 2);
        float dt_m = frcp(1.0f - rt_m1 * r_m);   // dt[N-1]

        #pragma unroll 4
        for (int m = NL - 1; m >= 2; --m) {
            size_t idxm1 = base + (size_t)(m - 1) * CCH;
            float s_m1 = s[idxm1];
            float r_m1 = r[idxm1];
            float t_m1 = t[idxm1];
            float a_m1 = a[idxm1];
            float ab_old = ab[idxm1];                // absorbed_down[m-1]

            float rt_m2 = SH_R(m - 2);
            float dt_m1 = frcp(1.0f - rt_m2 * r_m1); // dt[m-1]

            float s_up_m = dt_m * (s_m + s_m1 * r_m);
            float G = Fu + s_up_m;
            fu[base + (size_t)m * CCH] = G;

            float tdm1 = t_m1 * dt_m1;
            float au = G * a_m1 * (1.0f + rt_m2 * tdm1);
            ab[idxm1] = ab_old + au;
            Fu = G * tdm1;

            s_m = s_m1;
            r_m = r_m1;
            dt_m = dt_m1;
        }

        // m = 1 and m = 0 tail; after loop: s_m=s[1], r_m=r[1], dt_m=dt[1]
        float s0 = s[base];
        float t0 = t[base];
        float a0 = a[base];
        float s_up1 = dt_m * (s_m + s0 * r_m);
        float flux1 = Fu + s_up1;
        fu[base + CCH] = flux1;                  // flux_up[1]
        ab[base] = flux1 * a0;                   // absorbed[0] (down part = 0)
        fu[base] = flux1 * t0 + s0;              // flux_up[0]
    }

#undef SH_R
}

extern "C" void kernel_launch(void* const* d_in, const int* in_sizes, int n_in,
                              void* d_out, int out_size)
{
    const float* a = (const float*)d_in[0];
    const float* r = (const float*)d_in[1];
    const float* t = (const float*)d_in[2];
    const float* s = (const float*)d_in[3];
    float* out = (float*)d_out;

    cudaFuncSetAttribute(adding_doubling_kernel,
                         cudaFuncAttributeMaxDynamicSharedMemorySize,
                         (int)SMEM_BYTES);

    const int total = BCOL * CCH;                 // 262144 threads
    const int grid = (total + BLOCK - 1) / BLOCK; // 2048 blocks
    adding_doubling_kernel<<<grid, BLOCK, SMEM_BYTES>>>(a, r, t, s, out);
}